// round 4
// baseline (speedup 1.0000x reference)
#include <cuda_runtime.h>
#include <cuda_bf16.h>
#include <cstdint>

// WaveletPreprocessing: level-1 orthonormal Haar wavedec2 + waverec2 is an
// exact identity (perfect reconstruction, even dims, crop is a no-op) ->
// optimal kernel is a pure HBM->HBM copy (512 MiB read + 512 MiB write).
//
// R2 -> R3: persistent grid (152 SMs x 4 blocks, grid-stride over tiles)
// to eliminate ~13 wave transitions + partial-final-wave drain of the
// one-shot 8192-block launch. Inner tile identical to R2: 8 front-batched
// evict-first LDG.128 then 8 evict-first STG.128 per thread.

constexpr int UNROLL  = 8;
constexpr int THREADS = 512;
constexpr int TILE    = THREADS * UNROLL;   // 4096 float4 = 64 KiB per tile

__global__ void __launch_bounds__(THREADS, 4)
haar_identity_copy_kernel(const float4* __restrict__ src,
                          float4* __restrict__ dst,
                          long long n_vec)
{
    long long n_tiles = n_vec / TILE;               // full tiles (8192 here)
    long long tile    = blockIdx.x;
    long long gstride = gridDim.x;

    for (; tile < n_tiles; tile += gstride) {
        long long base = tile * TILE + threadIdx.x;
        float4 v[UNROLL];
#pragma unroll
        for (int k = 0; k < UNROLL; k++)
            v[k] = __ldcs(&src[base + (long long)k * THREADS]);
#pragma unroll
        for (int k = 0; k < UNROLL; k++)
            __stcs(&dst[base + (long long)k * THREADS], v[k]);
    }

    // Remainder float4s beyond the last full tile (none for n_vec = 2^25;
    // kept for shape-safety). Handled by block 0 only.
    long long rem_base = n_tiles * TILE;
    if (blockIdx.x == 0) {
        for (long long i = rem_base + threadIdx.x; i < n_vec; i += THREADS)
            __stcs(&dst[i], __ldcs(&src[i]));
    }
}

extern "C" void kernel_launch(void* const* d_in, const int* in_sizes, int n_in,
                              void* d_out, int out_size)
{
    const float* x = (const float*)d_in[0];
    float* out = (float*)d_out;

    long long n = (long long)in_sizes[0];   // 134,217,728 floats
    long long n_vec = n / 4;                // 33,554,432 float4 (exact)

    // Persistent grid: 152 SMs (GB300) x 4 resident blocks.
    int blocks = 152 * 4;

    haar_identity_copy_kernel<<<blocks, THREADS>>>(
        (const float4*)x, (float4*)out, n_vec);

    (void)n_in; (void)out_size;
}